// round 1
// baseline (speedup 1.0000x reference)
#include <cuda_runtime.h>
#include <cstddef>

#define BATCH   8192
#define IN_DIM  3072
#define HIDDEN  4096
#define OUT_DIM 10

// 128 MB scratch for the hidden activation (sanctioned __device__ global scratch).
__device__ float g_h[(size_t)BATCH * HIDDEN];

// ---------------------------------------------------------------------------
// GEMM1: h = relu(x @ W1 + b1)
// x:[B,K] row-major, W1:[K,N] row-major.
// Tiles: BM=BN=128, BK=8, 256 threads, 8x8 per-thread microtile.
// ---------------------------------------------------------------------------
__global__ __launch_bounds__(256, 2) void fc1_relu_kernel(
    const float* __restrict__ x, const float* __restrict__ W1,
    const float* __restrict__ b1)
{
    const int K = IN_DIM, N = HIDDEN;
    __shared__ float As[8][128];   // [k][m]  (x tile, transposed on store)
    __shared__ float Bs[8][128];   // [k][n]  (W1 tile)

    const int bm = blockIdx.y * 128;
    const int bn = blockIdx.x * 128;
    const int tid = (int)threadIdx.x;

    // 16x16 thread grid, each thread owns an 8x8 microtile
    const int tx = (tid & 15) * 8;   // n offset within tile
    const int ty = (tid >> 4) * 8;   // m offset within tile

    float acc[8][8];
    #pragma unroll
    for (int i = 0; i < 8; i++)
        #pragma unroll
        for (int j = 0; j < 8; j++) acc[i][j] = 0.f;

    // Load assignments:
    //   x tile  : 128 rows x 8 cols -> thread loads one float4: row=tid/2, col=(tid&1)*4
    //   W1 tile :   8 rows x 128 cols -> thread loads one float4: row=tid/32, col=(tid&31)*4
    const int xr = tid >> 1, xc = (tid & 1) * 4;
    const int wr = tid >> 5, wc = (tid & 31) * 4;

    const float* xp = x  + (size_t)(bm + xr) * K + xc;
    const float* wp = W1 + (size_t)wr * N + bn + wc;

    for (int k0 = 0; k0 < K; k0 += 8) {
        float4 xa = *(const float4*)(xp + k0);
        float4 wa = *(const float4*)(wp + (size_t)k0 * N);

        As[xc + 0][xr] = xa.x;
        As[xc + 1][xr] = xa.y;
        As[xc + 2][xr] = xa.z;
        As[xc + 3][xr] = xa.w;
        *(float4*)&Bs[wr][wc] = wa;
        __syncthreads();

        #pragma unroll
        for (int kk = 0; kk < 8; kk++) {
            float a[8], b[8];
            #pragma unroll
            for (int i = 0; i < 8; i++) a[i] = As[kk][ty + i];
            #pragma unroll
            for (int j = 0; j < 8; j++) b[j] = Bs[kk][tx + j];
            #pragma unroll
            for (int i = 0; i < 8; i++)
                #pragma unroll
                for (int j = 0; j < 8; j++)
                    acc[i][j] = fmaf(a[i], b[j], acc[i][j]);
        }
        __syncthreads();
    }

    // Epilogue: bias + relu, vectorized store to g_h
    #pragma unroll
    for (int i = 0; i < 8; i++) {
        const size_t row = (size_t)(bm + ty + i);
        #pragma unroll
        for (int j = 0; j < 8; j += 4) {
            const int col = bn + tx + j;
            float4 v;
            v.x = fmaxf(acc[i][j + 0] + b1[col + 0], 0.f);
            v.y = fmaxf(acc[i][j + 1] + b1[col + 1], 0.f);
            v.z = fmaxf(acc[i][j + 2] + b1[col + 2], 0.f);
            v.w = fmaxf(acc[i][j + 3] + b1[col + 3], 0.f);
            *(float4*)&g_h[row * N + col] = v;
        }
    }
}

// ---------------------------------------------------------------------------
// GEMM2: out = h @ W2 + b2   (skinny: N=10)
// One block per batch row; 128 threads strided over HIDDEN with float4 loads;
// per-thread 10-wide accumulators; warp + shared reduction (deterministic).
// ---------------------------------------------------------------------------
__global__ __launch_bounds__(128) void fc2_kernel(
    const float* __restrict__ W2, const float* __restrict__ b2,
    float* __restrict__ out)
{
    const int row = blockIdx.x;
    const int tid = (int)threadIdx.x;

    float acc[OUT_DIM];
    #pragma unroll
    for (int j = 0; j < OUT_DIM; j++) acc[j] = 0.f;

    const float4* hv = (const float4*)(g_h + (size_t)row * HIDDEN);
    for (int i = tid; i < HIDDEN / 4; i += 128) {
        const float4 v = hv[i];
        const int base = i * 4;
        const float* w0 = W2 + (size_t)(base + 0) * OUT_DIM;
        const float* w1 = W2 + (size_t)(base + 1) * OUT_DIM;
        const float* w2 = W2 + (size_t)(base + 2) * OUT_DIM;
        const float* w3 = W2 + (size_t)(base + 3) * OUT_DIM;
        #pragma unroll
        for (int j = 0; j < OUT_DIM; j++) {
            acc[j] = fmaf(v.x, __ldg(w0 + j), acc[j]);
            acc[j] = fmaf(v.y, __ldg(w1 + j), acc[j]);
            acc[j] = fmaf(v.z, __ldg(w2 + j), acc[j]);
            acc[j] = fmaf(v.w, __ldg(w3 + j), acc[j]);
        }
    }

    // warp reduction
    #pragma unroll
    for (int j = 0; j < OUT_DIM; j++)
        #pragma unroll
        for (int off = 16; off; off >>= 1)
            acc[j] += __shfl_xor_sync(0xffffffffu, acc[j], off);

    __shared__ float s[4][OUT_DIM];
    const int warp = tid >> 5, lane = tid & 31;
    if (lane == 0) {
        #pragma unroll
        for (int j = 0; j < OUT_DIM; j++) s[warp][j] = acc[j];
    }
    __syncthreads();

    if (tid < OUT_DIM) {
        float r = s[0][tid] + s[1][tid] + s[2][tid] + s[3][tid] + b2[tid];
        out[(size_t)row * OUT_DIM + tid] = r;
    }
}

// ---------------------------------------------------------------------------
extern "C" void kernel_launch(void* const* d_in, const int* in_sizes, int n_in,
                              void* d_out, int out_size) {
    const float* x  = (const float*)d_in[0];   // [8192, 3072]
    const float* W1 = (const float*)d_in[1];   // [3072, 4096]
    const float* b1 = (const float*)d_in[2];   // [4096]
    const float* W2 = (const float*)d_in[3];   // [4096, 10]
    const float* b2 = (const float*)d_in[4];   // [10]
    float* out = (float*)d_out;                // [8192, 10]
    (void)in_sizes; (void)n_in; (void)out_size;

    dim3 grid1(HIDDEN / 128, BATCH / 128);     // 32 x 64 = 2048 blocks
    fc1_relu_kernel<<<grid1, 256>>>(x, W1, b1);
    fc2_kernel<<<BATCH, 128>>>(W2, b2, out);
}

// round 3
// speedup vs baseline: 2.8426x; 2.8426x over previous
#include <cuda_runtime.h>
#include <cstdint>
#include <cstddef>

#define BATCH   8192
#define IN_DIM  3072
#define HIDDEN  4096
#define OUT_DIM 10

#define BM 128
#define BN 128
#define BK 16
#define NT (IN_DIM / BK)     // 192 k-tiles
#define AS_STRIDE 20         // conflict-free pad for [m][k] frag reads
#define BS_STRIDE 132        // conflict-free pad for [k][n] frag reads

// Scratch (sanctioned __device__ globals)
__device__ __align__(16) float g_h[(size_t)BATCH * HIDDEN];     // hidden acts
__device__ __align__(16) float g_w2t[OUT_DIM][HIDDEN];          // W2 transposed

// ---------------------------------------------------------------------------
// PTX helpers
// ---------------------------------------------------------------------------
__device__ __forceinline__ void cp_async16(void* smem, const void* gmem) {
    uint32_t s = (uint32_t)__cvta_generic_to_shared(smem);
    asm volatile("cp.async.cg.shared.global [%0], [%1], 16;\n" :: "r"(s), "l"(gmem));
}
__device__ __forceinline__ void cp_commit() { asm volatile("cp.async.commit_group;\n"); }
__device__ __forceinline__ void cp_wait0()  { asm volatile("cp.async.wait_group 0;\n"); }

__device__ __forceinline__ uint32_t f2tf32(float f) {
    uint32_t u;
    asm("cvt.rna.tf32.f32 %0, %1;" : "=r"(u) : "f"(f));
    return u;
}

__device__ __forceinline__ void mma_tf32(float& c0, float& c1, float& c2, float& c3,
                                         uint32_t a0, uint32_t a1, uint32_t a2, uint32_t a3,
                                         uint32_t b0, uint32_t b1) {
    asm volatile(
        "mma.sync.aligned.m16n8k8.row.col.f32.tf32.tf32.f32 "
        "{%0,%1,%2,%3}, {%4,%5,%6,%7}, {%8,%9}, {%0,%1,%2,%3};\n"
        : "+f"(c0), "+f"(c1), "+f"(c2), "+f"(c3)
        : "r"(a0), "r"(a1), "r"(a2), "r"(a3), "r"(b0), "r"(b1));
}

// ---------------------------------------------------------------------------
// GEMM1: h = relu(x @ W1 + b1) via m16n8k8 tf32 tensor-core MMA.
// Block 128x128, BK=16, 256 thr / 8 warps (warp tile 64x32), cp.async 2-stage.
// ---------------------------------------------------------------------------
__global__ __launch_bounds__(256) void fc1_mma_kernel(
    const float* __restrict__ x, const float* __restrict__ W1,
    const float* __restrict__ b1)
{
    __shared__ float As[2][BM][AS_STRIDE];   // x tile  [m][k], pad 20
    __shared__ float Bs[2][BK][BS_STRIDE];   // W1 tile [k][n], pad 132

    const int tid  = (int)threadIdx.x;
    const int warp = tid >> 5, lane = tid & 31;
    const int grp  = lane >> 2, tig = lane & 3;
    const int wm   = (warp >> 2) * 64;       // warp row base (0,64)
    const int wn   = (warp & 3) * 32;        // warp col base (0..96)
    const int bm   = blockIdx.y * BM;
    const int bn   = blockIdx.x * BN;

    // gmem->smem load assignments (2 float4 each per tile)
    const int ar = tid >> 1, ac = (tid & 1) * 8;     // As: 128 rows x 16 cols
    const int br = tid >> 4, bc = (tid & 15) * 8;    // Bs: 16 rows x 128 cols

    const float* xg = x  + (size_t)(bm + ar) * IN_DIM + ac;
    const float* wg = W1 + (size_t)br * HIDDEN + bn + bc;

    float c[4][4][4];
    #pragma unroll
    for (int mi = 0; mi < 4; mi++)
        #pragma unroll
        for (int ni = 0; ni < 4; ni++)
            #pragma unroll
            for (int r = 0; r < 4; r++) c[mi][ni][r] = 0.f;

    // prologue: stage tile 0
    {
        cp_async16(&As[0][ar][ac],     xg);
        cp_async16(&As[0][ar][ac + 4], xg + 4);
        cp_async16(&Bs[0][br][bc],     wg);
        cp_async16(&Bs[0][br][bc + 4], wg + 4);
        cp_commit();
    }

    int buf = 0;
    for (int kt = 0; kt < NT; kt++) {
        cp_wait0();
        __syncthreads();

        if (kt + 1 < NT) {
            const float* xa = xg + (kt + 1) * BK;
            const float* wa = wg + (size_t)(kt + 1) * BK * HIDDEN;
            const int nb = buf ^ 1;
            cp_async16(&As[nb][ar][ac],     xa);
            cp_async16(&As[nb][ar][ac + 4], xa + 4);
            cp_async16(&Bs[nb][br][bc],     wa);
            cp_async16(&Bs[nb][br][bc + 4], wa + 4);
            cp_commit();
        }

        // compute this k-tile: two k8 steps
        #pragma unroll
        for (int s = 0; s < 2; s++) {
            uint32_t a[4][4], b[4][2];
            const int k0 = s * 8;
            #pragma unroll
            for (int mi = 0; mi < 4; mi++) {
                const int row = wm + mi * 16;
                a[mi][0] = f2tf32(As[buf][row + grp    ][k0 + tig    ]);
                a[mi][1] = f2tf32(As[buf][row + grp + 8][k0 + tig    ]);
                a[mi][2] = f2tf32(As[buf][row + grp    ][k0 + tig + 4]);
                a[mi][3] = f2tf32(As[buf][row + grp + 8][k0 + tig + 4]);
            }
            #pragma unroll
            for (int ni = 0; ni < 4; ni++) {
                const int col = wn + ni * 8 + grp;
                b[ni][0] = f2tf32(Bs[buf][k0 + tig    ][col]);
                b[ni][1] = f2tf32(Bs[buf][k0 + tig + 4][col]);
            }
            #pragma unroll
            for (int mi = 0; mi < 4; mi++)
                #pragma unroll
                for (int ni = 0; ni < 4; ni++)
                    mma_tf32(c[mi][ni][0], c[mi][ni][1], c[mi][ni][2], c[mi][ni][3],
                             a[mi][0], a[mi][1], a[mi][2], a[mi][3],
                             b[ni][0], b[ni][1]);
        }
        buf ^= 1;
    }

    // epilogue: bias + relu, float2 stores
    #pragma unroll
    for (int mi = 0; mi < 4; mi++) {
        const int row0 = bm + wm + mi * 16 + grp;
        #pragma unroll
        for (int ni = 0; ni < 4; ni++) {
            const int col = bn + wn + ni * 8 + tig * 2;
            const float bx = __ldg(b1 + col), by = __ldg(b1 + col + 1);
            float2 v0, v1;
            v0.x = fmaxf(c[mi][ni][0] + bx, 0.f);
            v0.y = fmaxf(c[mi][ni][1] + by, 0.f);
            v1.x = fmaxf(c[mi][ni][2] + bx, 0.f);
            v1.y = fmaxf(c[mi][ni][3] + by, 0.f);
            *(float2*)&g_h[(size_t)row0 * HIDDEN + col]       = v0;
            *(float2*)&g_h[(size_t)(row0 + 8) * HIDDEN + col] = v1;
        }
    }
}

// ---------------------------------------------------------------------------
// W2 transpose: g_w2t[j][k] = W2[k][j]  (tiny: 40960 elems, enables float4 fc2)
// ---------------------------------------------------------------------------
__global__ void w2t_kernel(const float* __restrict__ W2) {
    const int i = blockIdx.x * 256 + (int)threadIdx.x;
    if (i < HIDDEN * OUT_DIM) {
        const int k = i / OUT_DIM, j = i % OUT_DIM;
        g_w2t[j][k] = W2[i];
    }
}

// ---------------------------------------------------------------------------
// GEMM2: out = h @ W2 + b2 using transposed W2 (all-float4 loads).
// One block per batch row, 128 threads, warp+shared reduction (deterministic).
// ---------------------------------------------------------------------------
__global__ __launch_bounds__(128) void fc2_kernel(
    const float* __restrict__ b2, float* __restrict__ out)
{
    const int row = blockIdx.x;
    const int tid = (int)threadIdx.x;

    float acc[OUT_DIM];
    #pragma unroll
    for (int j = 0; j < OUT_DIM; j++) acc[j] = 0.f;

    const float4* hv = (const float4*)(g_h + (size_t)row * HIDDEN);
    for (int i = tid; i < HIDDEN / 4; i += 128) {
        const float4 h4 = hv[i];
        #pragma unroll
        for (int j = 0; j < OUT_DIM; j++) {
            const float4 w = *(const float4*)&g_w2t[j][i * 4];
            float t = fmaf(h4.x, w.x, fmaf(h4.y, w.y, fmaf(h4.z, w.z, h4.w * w.w)));
            acc[j] += t;
        }
    }

    #pragma unroll
    for (int j = 0; j < OUT_DIM; j++)
        #pragma unroll
        for (int off = 16; off; off >>= 1)
            acc[j] += __shfl_xor_sync(0xffffffffu, acc[j], off);

    __shared__ float s[4][OUT_DIM];
    const int warp = tid >> 5, lane = tid & 31;
    if (lane == 0) {
        #pragma unroll
        for (int j = 0; j < OUT_DIM; j++) s[warp][j] = acc[j];
    }
    __syncthreads();

    if (tid < OUT_DIM) {
        out[(size_t)row * OUT_DIM + tid] =
            s[0][tid] + s[1][tid] + s[2][tid] + s[3][tid] + __ldg(b2 + tid);
    }
}

// ---------------------------------------------------------------------------
extern "C" void kernel_launch(void* const* d_in, const int* in_sizes, int n_in,
                              void* d_out, int out_size) {
    const float* x  = (const float*)d_in[0];   // [8192, 3072]
    const float* W1 = (const float*)d_in[1];   // [3072, 4096]
    const float* b1 = (const float*)d_in[2];   // [4096]
    const float* W2 = (const float*)d_in[3];   // [4096, 10]
    const float* b2 = (const float*)d_in[4];   // [10]
    float* out = (float*)d_out;                // [8192, 10]
    (void)in_sizes; (void)n_in; (void)out_size;

    dim3 grid1(HIDDEN / BN, BATCH / BM);       // 32 x 64 = 2048 blocks
    fc1_mma_kernel<<<grid1, 256>>>(x, W1, b1);
    w2t_kernel<<<(HIDDEN * OUT_DIM + 255) / 256, 256>>>(W2);
    fc2_kernel<<<BATCH, 128>>>(b2, out);
}

// round 6
// speedup vs baseline: 4.5358x; 1.5956x over previous
#include <cuda_runtime.h>
#include <cstdint>
#include <cstddef>

#define BATCH   8192
#define IN_DIM  3072
#define HIDDEN  4096
#define OUT_DIM 10

// fc1 tiling: CTA 256x128, warp 64x64 (8 warps), BK=32, 4-stage cp.async
#define BM 256
#define BN 128
#define BK 32
#define NT (IN_DIM / BK)                  // 96 k-tiles
#define NSTAGES 4
#define A_BYTES (BM * 128)                // 32 KB (256 rows x 128B)
#define B_BYTES (BN * 128)                // 16 KB
#define STAGE_BYTES (A_BYTES + B_BYTES)   // 48 KB
#define SMEM_TOTAL (NSTAGES * STAGE_BYTES)  // 192 KB

// ---------------- device scratch (sanctioned __device__ globals) -----------
__device__ __align__(16) float g_h  [(size_t)BATCH * HIDDEN];    // hidden acts
__device__ __align__(16) float g_xr [(size_t)BATCH * IN_DIM];    // x, tf32-rounded
__device__ __align__(16) float g_w1t[(size_t)HIDDEN * IN_DIM];   // W1^T, tf32-rounded
__device__ __align__(16) float g_w2t[OUT_DIM][HIDDEN];           // W2^T

// ---------------- helpers ---------------------------------------------------
#define SW128(o) ((o) ^ ((((uint32_t)(o)) >> 3) & 0x70))

__device__ __forceinline__ uint32_t smem_u32(const void* p) {
    uint32_t a;
    asm("{ .reg .u64 t; cvta.to.shared.u64 t, %1; cvt.u32.u64 %0, t; }" : "=r"(a) : "l"(p));
    return a;
}
__device__ __forceinline__ void cp16(uint32_t s, const void* g) {
    asm volatile("cp.async.cg.shared.global [%0], [%1], 16;\n" :: "r"(s), "l"(g));
}
__device__ __forceinline__ void cp_commit() { asm volatile("cp.async.commit_group;\n"); }
__device__ __forceinline__ void cp_wait3()  { asm volatile("cp.async.wait_group 3;\n"); }

__device__ __forceinline__ float tf32r(float f) {   // round-to-nearest tf32
    uint32_t u;
    asm("cvt.rna.tf32.f32 %0, %1;" : "=r"(u) : "f"(f));
    return __uint_as_float(u);
}

#define LDSM4(r0, r1, r2, r3, addr) \
    asm volatile("ldmatrix.sync.aligned.m8n8.x4.shared.b16 {%0,%1,%2,%3}, [%4];" \
                 : "=r"(r0), "=r"(r1), "=r"(r2), "=r"(r3) : "r"(addr))

__device__ __forceinline__ void mma_tf32(float& c0, float& c1, float& c2, float& c3,
                                         uint32_t a0, uint32_t a1, uint32_t a2, uint32_t a3,
                                         uint32_t b0, uint32_t b1) {
    asm volatile(
        "mma.sync.aligned.m16n8k8.row.col.f32.tf32.tf32.f32 "
        "{%0,%1,%2,%3}, {%4,%5,%6,%7}, {%8,%9}, {%0,%1,%2,%3};\n"
        : "+f"(c0), "+f"(c1), "+f"(c2), "+f"(c3)
        : "r"(a0), "r"(a1), "r"(a2), "r"(a3), "r"(b0), "r"(b1));
}

// ---------------------------------------------------------------------------
// Pre-pass 1: x -> g_xr rounded to tf32 (in-loop CVTs eliminated; exact HMMA)
// ---------------------------------------------------------------------------
__global__ __launch_bounds__(256) void xr_kernel(const float* __restrict__ x) {
    const size_t i = (size_t)blockIdx.x * 256 + threadIdx.x;   // float4 index
    const float4 v = ((const float4*)x)[i];
    float4 o;
    o.x = tf32r(v.x); o.y = tf32r(v.y); o.z = tf32r(v.z); o.w = tf32r(v.w);
    ((float4*)g_xr)[i] = o;
}

// ---------------------------------------------------------------------------
// Pre-pass 2: W1 [K][N] -> g_w1t [N][K], tf32-rounded. Tiled transpose.
// ---------------------------------------------------------------------------
__global__ __launch_bounds__(256) void w1t_kernel(const float* __restrict__ W1) {
    __shared__ float t[32][33];
    const int n0 = blockIdx.x * 32, k0 = blockIdx.y * 32;
    const int tx = threadIdx.x, ty = threadIdx.y;
    #pragma unroll
    for (int i = ty; i < 32; i += 8)
        t[i][tx] = W1[(size_t)(k0 + i) * HIDDEN + n0 + tx];
    __syncthreads();
    #pragma unroll
    for (int i = ty; i < 32; i += 8)
        g_w1t[(size_t)(n0 + i) * IN_DIM + k0 + tx] = tf32r(t[tx][i]);
}

// ---------------------------------------------------------------------------
// fc1: h = relu(xr @ w1t^T + b1), legacy tf32 mma.sync + ldmatrix + cp.async.
// ---------------------------------------------------------------------------
__global__ __launch_bounds__(256, 1) void fc1_mma_kernel(const float* __restrict__ b1)
{
    extern __shared__ __align__(1024) char smem[];
    const uint32_t smem_base = smem_u32(smem);

    const int tid  = (int)threadIdx.x;
    const int warp = tid >> 5, lane = tid & 31;
    const int grp  = lane >> 2, tig = lane & 3;
    const int wm   = (warp >> 1) * 64;     // 4 warps along M
    const int wn   = (warp & 1) * 64;      // 2 warps along N
    const int bm0  = blockIdx.y * BM;
    const int bn0  = blockIdx.x * BN;

    // per-lane ldmatrix address components
    const int aRow = (lane & 7) + ((lane >> 3) & 1) * 8;   // A: m0/m1 row pairs
    const int aByt = (lane >> 4) * 16;                      // A: k, k+4 halves
    const int bRow = ((lane >> 4) & 1) * 8 + (lane & 7);    // B: n 0-7 / 8-15
    const int bByt = ((lane >> 3) & 1) * 16;                // B: k, k+4 halves

    float c[4][8][4];
    #pragma unroll
    for (int mi = 0; mi < 4; mi++)
        #pragma unroll
        for (int ni = 0; ni < 8; ni++)
            #pragma unroll
            for (int r = 0; r < 4; r++) c[mi][ni][r] = 0.f;

    // --- stage loader: A 2048 + B 1024 16B-chunks, 12 per thread ------------
    auto load_tile = [&](int kt, int s) {
        const uint32_t sA = smem_base + s * STAGE_BYTES;
        const uint32_t sB = sA + A_BYTES;
        const float* gx = g_xr  + (size_t)bm0 * IN_DIM + kt * BK;
        const float* gw = g_w1t + (size_t)bn0 * IN_DIM + kt * BK;
        #pragma unroll
        for (int i = 0; i < 8; i++) {
            const int cidx = tid + i * 256;
            const int row = cidx >> 3, col = cidx & 7;
            cp16(sA + SW128(row * 128 + col * 16), gx + (size_t)row * IN_DIM + col * 4);
        }
        #pragma unroll
        for (int i = 0; i < 4; i++) {
            const int cidx = tid + i * 256;
            const int row = cidx >> 3, col = cidx & 7;
            cp16(sB + SW128(row * 128 + col * 16), gw + (size_t)row * IN_DIM + col * 4);
        }
        cp_commit();
    };

    load_tile(0, 0);
    load_tile(1, 1);
    load_tile(2, 2);
    load_tile(3, 3);

    for (int kt = 0; kt < NT; kt++) {
        const int s = kt & 3;
        cp_wait3();
        __syncthreads();

        const uint32_t sA = smem_base + s * STAGE_BYTES;
        const uint32_t sB = sA + A_BYTES;

        #pragma unroll
        for (int step = 0; step < 4; step++) {
            const int kb = step * 32;
            uint32_t a[4][4], b[8][2];
            #pragma unroll
            for (int mi = 0; mi < 4; mi++) {
                const uint32_t ad = sA + SW128((wm + mi * 16 + aRow) * 128 + kb + aByt);
                LDSM4(a[mi][0], a[mi][1], a[mi][2], a[mi][3], ad);
            }
            #pragma unroll
            for (int nj = 0; nj < 4; nj++) {
                const uint32_t bd = sB + SW128((wn + nj * 16 + bRow) * 128 + kb + bByt);
                LDSM4(b[2 * nj][0], b[2 * nj][1], b[2 * nj + 1][0], b[2 * nj + 1][1], bd);
            }
            #pragma unroll
            for (int mi = 0; mi < 4; mi++)
                #pragma unroll
                for (int ni = 0; ni < 8; ni++)
                    mma_tf32(c[mi][ni][0], c[mi][ni][1], c[mi][ni][2], c[mi][ni][3],
                             a[mi][0], a[mi][1], a[mi][2], a[mi][3],
                             b[ni][0], b[ni][1]);
        }
        __syncthreads();   // all warps done with stage s before overwrite

        if (kt + NSTAGES < NT) load_tile(kt + NSTAGES, s);
    }

    // epilogue: bias + relu, float2 stores
    float bx[8], by[8];
    #pragma unroll
    for (int ni = 0; ni < 8; ni++) {
        const int col = bn0 + wn + ni * 8 + tig * 2;
        bx[ni] = __ldg(b1 + col);
        by[ni] = __ldg(b1 + col + 1);
    }
    #pragma unroll
    for (int mi = 0; mi < 4; mi++) {
        const int row0 = bm0 + wm + mi * 16 + grp;
        #pragma unroll
        for (int ni = 0; ni < 8; ni++) {
            const int col = bn0 + wn + ni * 8 + tig * 2;
            float2 v0, v1;
            v0.x = fmaxf(c[mi][ni][0] + bx[ni], 0.f);
            v0.y = fmaxf(c[mi][ni][1] + by[ni], 0.f);
            v1.x = fmaxf(c[mi][ni][2] + bx[ni], 0.f);
            v1.y = fmaxf(c[mi][ni][3] + by[ni], 0.f);
            *(float2*)&g_h[(size_t)row0 * HIDDEN + col]       = v0;
            *(float2*)&g_h[(size_t)(row0 + 8) * HIDDEN + col] = v1;
        }
    }
}

// ---------------------------------------------------------------------------
// W2 transpose (tiny) + fc2 (skinny GEMM, float4 both sides)
// ---------------------------------------------------------------------------
__global__ void w2t_kernel(const float* __restrict__ W2) {
    const int i = blockIdx.x * 256 + (int)threadIdx.x;
    if (i < HIDDEN * OUT_DIM) {
        const int k = i / OUT_DIM, j = i % OUT_DIM;
        g_w2t[j][k] = W2[i];
    }
}

__global__ __launch_bounds__(128) void fc2_kernel(
    const float* __restrict__ b2, float* __restrict__ out)
{
    const int row = blockIdx.x;
    const int tid = (int)threadIdx.x;

    float acc[OUT_DIM];
    #pragma unroll
    for (int j = 0; j < OUT_DIM; j++) acc[j] = 0.f;

    const float4* hv = (const float4*)(g_h + (size_t)row * HIDDEN);
    for (int i = tid; i < HIDDEN / 4; i += 128) {
        const float4 h4 = hv[i];
        #pragma unroll
        for (int j = 0; j < OUT_DIM; j++) {
            const float4 w = *(const float4*)&g_w2t[j][i * 4];
            acc[j] += fmaf(h4.x, w.x, fmaf(h4.y, w.y, fmaf(h4.z, w.z, h4.w * w.w)));
        }
    }
    #pragma unroll
    for (int j = 0; j < OUT_DIM; j++)
        #pragma unroll
        for (int off = 16; off; off >>= 1)
            acc[j] += __shfl_xor_sync(0xffffffffu, acc[j], off);

    __shared__ float s[4][OUT_DIM];
    const int warp = tid >> 5, lane = tid & 31;
    if (lane == 0) {
        #pragma unroll
        for (int j = 0; j < OUT_DIM; j++) s[warp][j] = acc[j];
    }
    __syncthreads();
    if (tid < OUT_DIM) {
        out[(size_t)row * OUT_DIM + tid] =
            s[0][tid] + s[1][tid] + s[2][tid] + s[3][tid] + __ldg(b2 + tid);
    }
}

// ---------------------------------------------------------------------------
extern "C" void kernel_launch(void* const* d_in, const int* in_sizes, int n_in,
                              void* d_out, int out_size) {
    const float* x  = (const float*)d_in[0];   // [8192, 3072]
    const float* W1 = (const float*)d_in[1];   // [3072, 4096]
    const float* b1 = (const float*)d_in[2];   // [4096]
    const float* W2 = (const float*)d_in[3];   // [4096, 10]
    const float* b2 = (const float*)d_in[4];   // [10]
    float* out = (float*)d_out;                // [8192, 10]
    (void)in_sizes; (void)n_in; (void)out_size;

    cudaFuncSetAttribute(fc1_mma_kernel,
                         cudaFuncAttributeMaxDynamicSharedMemorySize, SMEM_TOTAL);

    xr_kernel<<<(BATCH * IN_DIM / 4 + 255) / 256, 256>>>(x);
    w1t_kernel<<<dim3(HIDDEN / 32, IN_DIM / 32), dim3(32, 8)>>>(W1);

    dim3 grid1(HIDDEN / BN, BATCH / BM);       // 32 x 32 = 1024 CTAs
    fc1_mma_kernel<<<grid1, 256, SMEM_TOTAL>>>(b1);

    w2t_kernel<<<(HIDDEN * OUT_DIM + 255) / 256, 256>>>(W2);
    fc2_kernel<<<BATCH, 128>>>(b2, out);
}

// round 7
// speedup vs baseline: 4.5996x; 1.0141x over previous
#include <cuda_runtime.h>
#include <cstdint>
#include <cstddef>

#define BATCH   8192
#define IN_DIM  3072
#define HIDDEN  4096
#define OUT_DIM 10

// fc1 tiling: CTA 256x128, warp 64x64 (8 warps), BK=32, 4-stage cp.async
#define BM 256
#define BN 128
#define BK 32
#define NT (IN_DIM / BK)                  // 96 k-tiles
#define NSTAGES 4
#define A_BYTES (BM * 128)                // 32 KB (256 rows x 128B)
#define B_BYTES (BN * 128)                // 16 KB
#define STAGE_BYTES (A_BYTES + B_BYTES)   // 48 KB
#define SMEM_TOTAL (NSTAGES * STAGE_BYTES)  // 192 KB

// ---------------- device scratch (sanctioned __device__ globals) -----------
__device__ __align__(16) float g_h  [(size_t)BATCH * HIDDEN];    // hidden acts
__device__ __align__(16) float g_xr [(size_t)BATCH * IN_DIM];    // x, tf32-rounded
__device__ __align__(16) float g_w1t[(size_t)HIDDEN * IN_DIM];   // W1^T, tf32-rounded
__device__ __align__(16) float g_w2t[OUT_DIM][HIDDEN];           // W2^T

// ---------------- helpers ---------------------------------------------------
#define SW128(o) ((o) ^ ((((uint32_t)(o)) >> 3) & 0x70))

__device__ __forceinline__ uint32_t smem_u32(const void* p) {
    uint32_t a;
    asm("{ .reg .u64 t; cvta.to.shared.u64 t, %1; cvt.u32.u64 %0, t; }" : "=r"(a) : "l"(p));
    return a;
}
__device__ __forceinline__ void cp16(uint32_t s, const void* g) {
    asm volatile("cp.async.cg.shared.global [%0], [%1], 16;\n" :: "r"(s), "l"(g));
}
__device__ __forceinline__ void cp_commit() { asm volatile("cp.async.commit_group;\n"); }
__device__ __forceinline__ void cp_wait2()  { asm volatile("cp.async.wait_group 2;\n"); }

__device__ __forceinline__ float tf32r(float f) {   // round-to-nearest tf32
    uint32_t u;
    asm("cvt.rna.tf32.f32 %0, %1;" : "=r"(u) : "f"(f));
    return __uint_as_float(u);
}

#define LDSM4(r0, r1, r2, r3, addr) \
    asm volatile("ldmatrix.sync.aligned.m8n8.x4.shared.b16 {%0,%1,%2,%3}, [%4];" \
                 : "=r"(r0), "=r"(r1), "=r"(r2), "=r"(r3) : "r"(addr))

__device__ __forceinline__ void mma_tf32(float& c0, float& c1, float& c2, float& c3,
                                         uint32_t a0, uint32_t a1, uint32_t a2, uint32_t a3,
                                         uint32_t b0, uint32_t b1) {
    asm volatile(
        "mma.sync.aligned.m16n8k8.row.col.f32.tf32.tf32.f32 "
        "{%0,%1,%2,%3}, {%4,%5,%6,%7}, {%8,%9}, {%0,%1,%2,%3};\n"
        : "+f"(c0), "+f"(c1), "+f"(c2), "+f"(c3)
        : "r"(a0), "r"(a1), "r"(a2), "r"(a3), "r"(b0), "r"(b1));
}

// ---------------------------------------------------------------------------
// Pre-pass 1: x -> g_xr rounded to tf32 (in-loop CVTs eliminated; exact HMMA)
// ---------------------------------------------------------------------------
__global__ __launch_bounds__(256) void xr_kernel(const float* __restrict__ x) {
    const size_t i = (size_t)blockIdx.x * 256 + threadIdx.x;   // float4 index
    const float4 v = ((const float4*)x)[i];
    float4 o;
    o.x = tf32r(v.x); o.y = tf32r(v.y); o.z = tf32r(v.z); o.w = tf32r(v.w);
    ((float4*)g_xr)[i] = o;
}

// ---------------------------------------------------------------------------
// Pre-pass 2: W1 [K][N] -> g_w1t [N][K], tf32-rounded. Tiled transpose.
// ---------------------------------------------------------------------------
__global__ __launch_bounds__(256) void w1t_kernel(const float* __restrict__ W1) {
    __shared__ float t[32][33];
    const int n0 = blockIdx.x * 32, k0 = blockIdx.y * 32;
    const int tx = threadIdx.x, ty = threadIdx.y;
    #pragma unroll
    for (int i = ty; i < 32; i += 8)
        t[i][tx] = W1[(size_t)(k0 + i) * HIDDEN + n0 + tx];
    __syncthreads();
    #pragma unroll
    for (int i = ty; i < 32; i += 8)
        g_w1t[(size_t)(n0 + i) * IN_DIM + k0 + tx] = tf32r(t[tx][i]);
}

// ---------------------------------------------------------------------------
// fc1: h = relu(xr @ w1t^T + b1), legacy tf32 mma.sync + ldmatrix + cp.async.
// Single-barrier multistage pipeline: one __syncthreads per k-tile; loads for
// tile kt+3 are issued right after the barrier (into the stage freed by it).
// ---------------------------------------------------------------------------
__global__ __launch_bounds__(256, 1) void fc1_mma_kernel(const float* __restrict__ b1)
{
    extern __shared__ __align__(1024) char smem[];
    const uint32_t smem_base = smem_u32(smem);

    const int tid  = (int)threadIdx.x;
    const int warp = tid >> 5, lane = tid & 31;
    const int grp  = lane >> 2, tig = lane & 3;
    const int wm   = (warp >> 1) * 64;     // 4 warps along M
    const int wn   = (warp & 1) * 64;      // 2 warps along N
    const int bm0  = blockIdx.y * BM;
    const int bn0  = blockIdx.x * BN;

    // per-lane ldmatrix address components
    const int aRow = (lane & 7) + ((lane >> 3) & 1) * 8;   // A: m0/m1 row pairs
    const int aByt = (lane >> 4) * 16;                      // A: k, k+4 halves
    const int bRow = ((lane >> 4) & 1) * 8 + (lane & 7);    // B: n 0-7 / 8-15
    const int bByt = ((lane >> 3) & 1) * 16;                // B: k, k+4 halves

    float c[4][8][4];
    #pragma unroll
    for (int mi = 0; mi < 4; mi++)
        #pragma unroll
        for (int ni = 0; ni < 8; ni++)
            #pragma unroll
            for (int r = 0; r < 4; r++) c[mi][ni][r] = 0.f;

    // --- stage loader: A 2048 + B 1024 16B-chunks, 12 per thread ------------
    auto load_tile = [&](int kt, int s) {
        const uint32_t sA = smem_base + s * STAGE_BYTES;
        const uint32_t sB = sA + A_BYTES;
        const float* gx = g_xr  + (size_t)bm0 * IN_DIM + kt * BK;
        const float* gw = g_w1t + (size_t)bn0 * IN_DIM + kt * BK;
        #pragma unroll
        for (int i = 0; i < 8; i++) {
            const int cidx = tid + i * 256;
            const int row = cidx >> 3, col = cidx & 7;
            cp16(sA + SW128(row * 128 + col * 16), gx + (size_t)row * IN_DIM + col * 4);
        }
        #pragma unroll
        for (int i = 0; i < 4; i++) {
            const int cidx = tid + i * 256;
            const int row = cidx >> 3, col = cidx & 7;
            cp16(sB + SW128(row * 128 + col * 16), gw + (size_t)row * IN_DIM + col * 4);
        }
        cp_commit();
    };

    // prologue: 3 tiles in flight
    load_tile(0, 0);
    load_tile(1, 1);
    load_tile(2, 2);

    for (int kt = 0; kt < NT; kt++) {
        const int s = kt & 3;
        cp_wait2();          // tile kt's group complete (<=2 newer pending)
        __syncthreads();     // data visible to all warps; also proves all warps
                             // finished tile kt-1 => stage (kt-1)&3 is free

        if (kt + 3 < NT) load_tile(kt + 3, (kt + 3) & 3);  // == stage (kt-1)&3

        const uint32_t sA = smem_base + s * STAGE_BYTES;
        const uint32_t sB = sA + A_BYTES;

        #pragma unroll
        for (int step = 0; step < 4; step++) {
            const int kb = step * 32;
            uint32_t a[4][4], b[8][2];
            #pragma unroll
            for (int mi = 0; mi < 4; mi++) {
                const uint32_t ad = sA + SW128((wm + mi * 16 + aRow) * 128 + kb + aByt);
                LDSM4(a[mi][0], a[mi][1], a[mi][2], a[mi][3], ad);
            }
            #pragma unroll
            for (int nj = 0; nj < 4; nj++) {
                const uint32_t bd = sB + SW128((wn + nj * 16 + bRow) * 128 + kb + bByt);
                LDSM4(b[2 * nj][0], b[2 * nj][1], b[2 * nj + 1][0], b[2 * nj + 1][1], bd);
            }
            #pragma unroll
            for (int mi = 0; mi < 4; mi++)
                #pragma unroll
                for (int ni = 0; ni < 8; ni++)
                    mma_tf32(c[mi][ni][0], c[mi][ni][1], c[mi][ni][2], c[mi][ni][3],
                             a[mi][0], a[mi][1], a[mi][2], a[mi][3],
                             b[ni][0], b[ni][1]);
        }
    }

    // epilogue: bias + relu, float2 stores
    float bx[8], by[8];
    #pragma unroll
    for (int ni = 0; ni < 8; ni++) {
        const int col = bn0 + wn + ni * 8 + tig * 2;
        bx[ni] = __ldg(b1 + col);
        by[ni] = __ldg(b1 + col + 1);
    }
    #pragma unroll
    for (int mi = 0; mi < 4; mi++) {
        const int row0 = bm0 + wm + mi * 16 + grp;
        #pragma unroll
        for (int ni = 0; ni < 8; ni++) {
            const int col = bn0 + wn + ni * 8 + tig * 2;
            float2 v0, v1;
            v0.x = fmaxf(c[mi][ni][0] + bx[ni], 0.f);
            v0.y = fmaxf(c[mi][ni][1] + by[ni], 0.f);
            v1.x = fmaxf(c[mi][ni][2] + bx[ni], 0.f);
            v1.y = fmaxf(c[mi][ni][3] + by[ni], 0.f);
            *(float2*)&g_h[(size_t)row0 * HIDDEN + col]       = v0;
            *(float2*)&g_h[(size_t)(row0 + 8) * HIDDEN + col] = v1;
        }
    }
}

// ---------------------------------------------------------------------------
// W2 transpose (tiny)
// ---------------------------------------------------------------------------
__global__ void w2t_kernel(const float* __restrict__ W2) {
    const int i = blockIdx.x * 256 + (int)threadIdx.x;
    if (i < HIDDEN * OUT_DIM) {
        const int k = i / OUT_DIM, j = i % OUT_DIM;
        g_w2t[j][k] = W2[i];
    }
}

// ---------------------------------------------------------------------------
// fc2: warp-per-row (8 rows/CTA), pure shuffle reduction, no shared memory.
// ---------------------------------------------------------------------------
__global__ __launch_bounds__(256) void fc2_kernel(
    const float* __restrict__ b2, float* __restrict__ out)
{
    const int warp = (int)threadIdx.x >> 5, lane = (int)threadIdx.x & 31;
    const int row  = blockIdx.x * 8 + warp;

    float acc[OUT_DIM];
    #pragma unroll
    for (int j = 0; j < OUT_DIM; j++) acc[j] = 0.f;

    const float4* hv = (const float4*)(g_h + (size_t)row * HIDDEN);
    #pragma unroll 4
    for (int i = lane; i < HIDDEN / 4; i += 32) {
        const float4 h4 = hv[i];
        #pragma unroll
        for (int j = 0; j < OUT_DIM; j++) {
            const float4 w = *(const float4*)&g_w2t[j][i * 4];
            acc[j] += fmaf(h4.x, w.x, fmaf(h4.y, w.y, fmaf(h4.z, w.z, h4.w * w.w)));
        }
    }
    #pragma unroll
    for (int j = 0; j < OUT_DIM; j++)
        #pragma unroll
        for (int off = 16; off; off >>= 1)
            acc[j] += __shfl_xor_sync(0xffffffffu, acc[j], off);

    if (lane == 0) {
        #pragma unroll
        for (int j = 0; j < OUT_DIM; j++)
            out[(size_t)row * OUT_DIM + j] = acc[j] + __ldg(b2 + j);
    }
}

// ---------------------------------------------------------------------------
extern "C" void kernel_launch(void* const* d_in, const int* in_sizes, int n_in,
                              void* d_out, int out_size) {
    const float* x  = (const float*)d_in[0];   // [8192, 3072]
    const float* W1 = (const float*)d_in[1];   // [3072, 4096]
    const float* b1 = (const float*)d_in[2];   // [4096]
    const float* W2 = (const float*)d_in[3];   // [4096, 10]
    const float* b2 = (const float*)d_in[4];   // [10]
    float* out = (float*)d_out;                // [8192, 10]
    (void)in_sizes; (void)n_in; (void)out_size;

    cudaFuncSetAttribute(fc1_mma_kernel,
                         cudaFuncAttributeMaxDynamicSharedMemorySize, SMEM_TOTAL);

    xr_kernel<<<(BATCH * IN_DIM / 4 + 255) / 256, 256>>>(x);
    w1t_kernel<<<dim3(HIDDEN / 32, IN_DIM / 32), dim3(32, 8)>>>(W1);

    dim3 grid1(HIDDEN / BN, BATCH / BM);       // 32 x 32 = 1024 CTAs
    fc1_mma_kernel<<<grid1, 256, SMEM_TOTAL>>>(b1);

    w2t_kernel<<<(HIDDEN * OUT_DIM + 255) / 256, 256>>>(W2);
    fc2_kernel<<<BATCH / 8, 256>>>(b2, out);
}